// round 1
// baseline (speedup 1.0000x reference)
#include <cuda_runtime.h>
#include <cstddef>

// Problem constants
#define BATCH 8
#define LEN   4096
#define IND   512
#define ST    256
#define OUTD  512

#define CHUNK 256
#define NCH   (LEN / CHUNK)   // 16

// Scratch in device globals (no allocation allowed)
__device__ float g_uB[(size_t)BATCH * LEN * ST];      // 32 MB
__device__ float g_x [(size_t)BATCH * LEN * ST];      // 32 MB
__device__ float g_carry[BATCH * NCH * ST];
__device__ float g_init [BATCH * NCH * ST];

// ---------------------------------------------------------------------------
// Tiled fp32 GEMM: Cm[M,N] = A[M,K] @ Bm[K,N], all row-major.
// BM=BN=64, BK=16, 256 threads, 4x4 per-thread microtile.
// M % 64 == 0, N % 64 == 0, K % 16 == 0 guaranteed by problem shapes.
// ---------------------------------------------------------------------------
#define BM 64
#define BN 64
#define BK 16

__global__ __launch_bounds__(256)
void gemm_kernel(const float* __restrict__ A, const float* __restrict__ Bm,
                 float* __restrict__ Cm, int M, int N, int K) {
    __shared__ float As[BK][BM];
    __shared__ float Bs[BK][BN];

    const int tid = threadIdx.x;
    const int tx = tid & 15;        // 0..15 -> n
    const int ty = tid >> 4;        // 0..15 -> m
    const int rowBase = blockIdx.y * BM;
    const int colBase = blockIdx.x * BN;

    // A-tile load: 64 rows x 16 cols, float4 along K per thread
    const int aRow = tid >> 2;          // 0..63
    const int aCol = (tid & 3) * 4;     // 0,4,8,12
    // B-tile load: 16 rows x 64 cols, float4 along N per thread
    const int bRow = tid >> 4;          // 0..15
    const int bCol = (tid & 15) * 4;    // 0..60

    float acc[4][4] = {};

    for (int k0 = 0; k0 < K; k0 += BK) {
        float4 av = *(const float4*)&A[(size_t)(rowBase + aRow) * K + k0 + aCol];
        As[aCol + 0][aRow] = av.x;
        As[aCol + 1][aRow] = av.y;
        As[aCol + 2][aRow] = av.z;
        As[aCol + 3][aRow] = av.w;
        float4 bv = *(const float4*)&Bm[(size_t)(k0 + bRow) * N + colBase + bCol];
        *(float4*)&Bs[bRow][bCol] = bv;
        __syncthreads();

        #pragma unroll
        for (int k = 0; k < BK; k++) {
            float ra[4], rb[4];
            #pragma unroll
            for (int i = 0; i < 4; i++) ra[i] = As[k][ty * 4 + i];
            #pragma unroll
            for (int j = 0; j < 4; j++) rb[j] = Bs[k][tx * 4 + j];
            #pragma unroll
            for (int i = 0; i < 4; i++)
                #pragma unroll
                for (int j = 0; j < 4; j++)
                    acc[i][j] = fmaf(ra[i], rb[j], acc[i][j]);
        }
        __syncthreads();
    }

    #pragma unroll
    for (int i = 0; i < 4; i++) {
        float4 v = make_float4(acc[i][0], acc[i][1], acc[i][2], acc[i][3]);
        *(float4*)&Cm[(size_t)(rowBase + ty * 4 + i) * N + colBase + tx * 4] = v;
    }
}

// ---------------------------------------------------------------------------
// Scan pass 1: per-chunk carry with zero initial state.
// grid = BATCH*NCH blocks, 256 threads (= one state index each).
// ---------------------------------------------------------------------------
__global__ __launch_bounds__(ST)
void scan1_kernel(const float* __restrict__ A) {
    const int n = threadIdx.x;
    const int c = blockIdx.x % NCH;
    const int b = blockIdx.x / NCH;
    const float a = A[n];
    const float* p = g_uB + ((size_t)(b * LEN + c * CHUNK)) * ST + n;
    float s = 0.0f;
    #pragma unroll 8
    for (int t = 0; t < CHUNK; t++) {
        s = fmaf(a, s, p[(size_t)t * ST]);
    }
    g_carry[(b * NCH + c) * ST + n] = s;
}

// ---------------------------------------------------------------------------
// Scan pass 2: inter-chunk exclusive prefix combine.
// init[c] = state before chunk c (i.e., x_{c*CHUNK - 1}); init[0] = x0.
// grid = BATCH blocks, 256 threads.
// ---------------------------------------------------------------------------
__global__ __launch_bounds__(ST)
void scan2_kernel(const float* __restrict__ A, const float* __restrict__ x0) {
    const int n = threadIdx.x;
    const int b = blockIdx.x;
    const float a = A[n];
    float aL = a;
    #pragma unroll
    for (int i = 0; i < 8; i++) aL *= aL;   // a^256
    float s = x0[b * ST + n];
    #pragma unroll
    for (int c = 0; c < NCH; c++) {
        g_init[(b * NCH + c) * ST + n] = s;
        s = fmaf(aL, s, g_carry[(b * NCH + c) * ST + n]);
    }
}

// ---------------------------------------------------------------------------
// Scan pass 3: full scan per chunk from true initial state, writes x.
// Last chunk also writes x[:, -1] to the output tail.
// ---------------------------------------------------------------------------
__global__ __launch_bounds__(ST)
void scan3_kernel(const float* __restrict__ A, float* __restrict__ xlast) {
    const int n = threadIdx.x;
    const int c = blockIdx.x % NCH;
    const int b = blockIdx.x / NCH;
    const float a = A[n];
    float s = g_init[(b * NCH + c) * ST + n];
    const size_t base = ((size_t)(b * LEN + c * CHUNK)) * ST + n;
    #pragma unroll 8
    for (int t = 0; t < CHUNK; t++) {
        s = fmaf(a, s, g_uB[base + (size_t)t * ST]);
        g_x[base + (size_t)t * ST] = s;
    }
    if (c == NCH - 1) {
        xlast[b * ST + n] = s;
    }
}

// ---------------------------------------------------------------------------
// kernel_launch
// Inputs (metadata order): u [8,4096,512], x0 [8,256], A [256],
//                          B [512,256], C [256,512]
// Output: y [8,4096,512] flattened, then x_last [8,256].
// ---------------------------------------------------------------------------
extern "C" void kernel_launch(void* const* d_in, const int* in_sizes, int n_in,
                              void* d_out, int out_size) {
    const float* u  = (const float*)d_in[0];
    const float* x0 = (const float*)d_in[1];
    const float* A  = (const float*)d_in[2];
    const float* B  = (const float*)d_in[3];
    const float* C  = (const float*)d_in[4];

    float* y = (float*)d_out;
    float* xlast = y + (size_t)BATCH * LEN * OUTD;

    float* uB_ptr = nullptr;
    float* x_ptr  = nullptr;
    cudaGetSymbolAddress((void**)&uB_ptr, g_uB);
    cudaGetSymbolAddress((void**)&x_ptr,  g_x);

    const int M = BATCH * LEN;   // 32768

    // GEMM1: uB = u @ B   [M,512] @ [512,256]
    {
        dim3 grid(ST / BN, M / BM);
        gemm_kernel<<<grid, 256>>>(u, B, uB_ptr, M, ST, IND);
    }

    // Scan
    scan1_kernel<<<BATCH * NCH, ST>>>(A);
    scan2_kernel<<<BATCH, ST>>>(A, x0);
    scan3_kernel<<<BATCH * NCH, ST>>>(A, xlast);

    // GEMM2: y = x @ C    [M,256] @ [256,512]
    {
        dim3 grid(OUTD / BN, M / BM);
        gemm_kernel<<<grid, 256>>>(x_ptr, C, y, M, OUTD, ST);
    }
}

// round 2
// speedup vs baseline: 1.0154x; 1.0154x over previous
#include <cuda_runtime.h>
#include <cstddef>

// Problem constants
#define BATCH 8
#define LEN   4096
#define IND   512
#define ST    256
#define OUTD  512

#define CHUNK 64
#define NCH   (LEN / CHUNK)   // 64

// Scratch in device globals (no allocation allowed)
__device__ float g_uB[(size_t)BATCH * LEN * ST];      // 32 MB
__device__ float g_x [(size_t)BATCH * LEN * ST];      // 32 MB
__device__ float g_carry[BATCH * NCH * ST];
__device__ float g_init [BATCH * NCH * ST];

// ---------------------------------------------------------------------------
// Tiled fp32 GEMM: Cm[M,N] = A[M,K] @ Bm[K,N], row-major.
// 128x128x16 tile, 256 threads, 8x8 microtile, double-buffered smem.
// Requires M%128==0, N%128==0, K%16==0 (holds: M=32768, N in {256,512}, K in {512,256}).
// ---------------------------------------------------------------------------
#define GBM 128
#define GBN 128
#define GBK 16

__global__ __launch_bounds__(256)
void gemm128(const float* __restrict__ A, const float* __restrict__ Bm,
             float* __restrict__ Cm, int M, int N, int K) {
    __shared__ float As[2][GBK][GBM];
    __shared__ float Bs[2][GBK][GBN];
    const int tid = threadIdx.x;
    const int rowBase = blockIdx.y * GBM;
    const int colBase = blockIdx.x * GBN;

    // A load: 128 rows x 16 cols; each thread 2 float4 along K (rows r, r+64)
    const int aRow = tid >> 2;           // 0..63
    const int aCol = (tid & 3) * 4;      // 0,4,8,12
    // B load: 16 rows x 128 cols; each thread 2 float4 along N (rows r, r+8)
    const int bRow = tid >> 5;           // 0..7
    const int bCol = (tid & 31) * 4;     // 0..124

    const int tm = (tid >> 4) * 8;       // 0..120
    const int tn = (tid & 15) * 8;       // 0..120

    float acc[8][8] = {};

    // prologue: tile 0 -> buffer 0
    {
        const float* Ag = A + (size_t)(rowBase + aRow) * K + aCol;
        float4 a0 = *(const float4*)Ag;
        float4 a1 = *(const float4*)(Ag + (size_t)64 * K);
        #pragma unroll
        for (int i = 0; i < 4; i++) {
            As[0][aCol + i][aRow]      = ((const float*)&a0)[i];
            As[0][aCol + i][aRow + 64] = ((const float*)&a1)[i];
        }
        const float* Bg = Bm + (size_t)bRow * N + colBase + bCol;
        *(float4*)&Bs[0][bRow][bCol]     = *(const float4*)Bg;
        *(float4*)&Bs[0][bRow + 8][bCol] = *(const float4*)(Bg + (size_t)8 * N);
    }
    __syncthreads();

    const int nk = K / GBK;
    for (int kt = 0; kt < nk; kt++) {
        const int cur = kt & 1;
        const int nxt = cur ^ 1;
        float4 pa0, pa1, pb0, pb1;
        const bool havenext = (kt + 1 < nk);
        if (havenext) {
            const int k0 = (kt + 1) * GBK;
            const float* Ag = A + (size_t)(rowBase + aRow) * K + k0 + aCol;
            pa0 = *(const float4*)Ag;
            pa1 = *(const float4*)(Ag + (size_t)64 * K);
            const float* Bg = Bm + (size_t)(k0 + bRow) * N + colBase + bCol;
            pb0 = *(const float4*)Bg;
            pb1 = *(const float4*)(Bg + (size_t)8 * N);
        }

        #pragma unroll
        for (int k = 0; k < GBK; k++) {
            float ra[8], rb[8];
            *(float4*)&ra[0] = *(const float4*)&As[cur][k][tm];
            *(float4*)&ra[4] = *(const float4*)&As[cur][k][tm + 4];
            *(float4*)&rb[0] = *(const float4*)&Bs[cur][k][tn];
            *(float4*)&rb[4] = *(const float4*)&Bs[cur][k][tn + 4];
            #pragma unroll
            for (int i = 0; i < 8; i++)
                #pragma unroll
                for (int j = 0; j < 8; j++)
                    acc[i][j] = fmaf(ra[i], rb[j], acc[i][j]);
        }

        if (havenext) {
            #pragma unroll
            for (int i = 0; i < 4; i++) {
                As[nxt][aCol + i][aRow]      = ((const float*)&pa0)[i];
                As[nxt][aCol + i][aRow + 64] = ((const float*)&pa1)[i];
            }
            *(float4*)&Bs[nxt][bRow][bCol]     = pb0;
            *(float4*)&Bs[nxt][bRow + 8][bCol] = pb1;
        }
        __syncthreads();
    }

    #pragma unroll
    for (int i = 0; i < 8; i++) {
        float* Cp = &Cm[(size_t)(rowBase + tm + i) * N + colBase + tn];
        *(float4*)Cp       = make_float4(acc[i][0], acc[i][1], acc[i][2], acc[i][3]);
        *(float4*)(Cp + 4) = make_float4(acc[i][4], acc[i][5], acc[i][6], acc[i][7]);
    }
}

// ---------------------------------------------------------------------------
// Scan pass 1: per-chunk carry with zero initial state.
// grid = BATCH*NCH (512), block = ST threads (one per state channel).
// ---------------------------------------------------------------------------
__global__ __launch_bounds__(ST)
void scan1_kernel(const float* __restrict__ A) {
    const int n = threadIdx.x;
    const int c = blockIdx.x % NCH;
    const int b = blockIdx.x / NCH;
    const float a = A[n];
    const float* p = g_uB + ((size_t)(b * LEN + c * CHUNK)) * ST + n;
    float s = 0.0f;
    #pragma unroll 8
    for (int t = 0; t < CHUNK; t++) {
        s = fmaf(a, s, p[(size_t)t * ST]);
    }
    g_carry[(b * NCH + c) * ST + n] = s;
}

// ---------------------------------------------------------------------------
// Scan pass 2: inter-chunk exclusive prefix combine.
// init[c] = state before chunk c; init[0] = x0. grid = BATCH, block = ST.
// ---------------------------------------------------------------------------
__global__ __launch_bounds__(ST)
void scan2_kernel(const float* __restrict__ A, const float* __restrict__ x0) {
    const int n = threadIdx.x;
    const int b = blockIdx.x;
    const float a = A[n];
    float aL = a;
    #pragma unroll
    for (int i = 0; i < 6; i++) aL *= aL;   // a^64 = a^(2^6)
    float s = x0[b * ST + n];
    #pragma unroll
    for (int c = 0; c < NCH; c++) {
        g_init[(b * NCH + c) * ST + n] = s;
        s = fmaf(aL, s, g_carry[(b * NCH + c) * ST + n]);
    }
}

// ---------------------------------------------------------------------------
// Scan pass 3: full rescan per chunk from true initial state, writes x.
// Last chunk also writes x[:, -1] to the output tail.
// ---------------------------------------------------------------------------
__global__ __launch_bounds__(ST)
void scan3_kernel(const float* __restrict__ A, float* __restrict__ xlast) {
    const int n = threadIdx.x;
    const int c = blockIdx.x % NCH;
    const int b = blockIdx.x / NCH;
    const float a = A[n];
    float s = g_init[(b * NCH + c) * ST + n];
    const size_t base = ((size_t)(b * LEN + c * CHUNK)) * ST + n;
    #pragma unroll 8
    for (int t = 0; t < CHUNK; t++) {
        s = fmaf(a, s, g_uB[base + (size_t)t * ST]);
        g_x[base + (size_t)t * ST] = s;
    }
    if (c == NCH - 1) {
        xlast[b * ST + n] = s;
    }
}

// ---------------------------------------------------------------------------
// kernel_launch
// Inputs (metadata order): u [8,4096,512], x0 [8,256], A [256],
//                          B [512,256], C [256,512]
// Output: y [8,4096,512] flattened, then x_last [8,256].
// ---------------------------------------------------------------------------
extern "C" void kernel_launch(void* const* d_in, const int* in_sizes, int n_in,
                              void* d_out, int out_size) {
    const float* u  = (const float*)d_in[0];
    const float* x0 = (const float*)d_in[1];
    const float* A  = (const float*)d_in[2];
    const float* B  = (const float*)d_in[3];
    const float* C  = (const float*)d_in[4];

    float* y = (float*)d_out;
    float* xlast = y + (size_t)BATCH * LEN * OUTD;

    float* uB_ptr = nullptr;
    float* x_ptr  = nullptr;
    cudaGetSymbolAddress((void**)&uB_ptr, g_uB);
    cudaGetSymbolAddress((void**)&x_ptr,  g_x);

    const int M = BATCH * LEN;   // 32768

    // GEMM1: uB = u @ B   [32768,512] @ [512,256]
    {
        dim3 grid(ST / GBN, M / GBM);
        gemm128<<<grid, 256>>>(u, B, uB_ptr, M, ST, IND);
    }

    // Scan
    scan1_kernel<<<BATCH * NCH, ST>>>(A);
    scan2_kernel<<<BATCH, ST>>>(A, x0);
    scan3_kernel<<<BATCH * NCH, ST>>>(A, xlast);

    // GEMM2: y = x @ C    [32768,256] @ [256,512]
    {
        dim3 grid(OUTD / GBN, M / GBM);
        gemm128<<<grid, 256>>>(x_ptr, C, y, M, OUTD, ST);
    }
}